// round 15
// baseline (speedup 1.0000x reference)
#include <cuda_runtime.h>
#include <cstdint>

// x: [16, 64, 128, 128] (B, C, H, W), HX = HY = 64.
// Pass 1 (fused): read x, proj+scan along w -> g_mid[(b,h)][w][j]
// Pass 2 (fused): read g_mid, proj+scan along h -> g_buf[(b,w)][h][j2]
// Transpose: g_buf -> out[b][j][h][w]

using ull = unsigned long long;

__device__ float g_mid[2048 * 128 * 64];   // pass-1 output  [(b,h)][w][j]
__device__ float g_buf[2048 * 128 * 64];   // pass-2 output  [(b,w)][h][j2]
__device__ float g_WTx[64 * 64];           // Wih_x^T: [c][j]
__device__ float g_WTy[64 * 64];           // Wih_y^T: [j][j2]
__device__ ull   g_bsdx[64];               // dup'd bias sums
__device__ ull   g_bsdy[64];

__device__ __forceinline__ ull ffma2(ull a, ull b, ull c) {
    ull d;
    asm("fma.rn.f32x2 %0, %1, %2, %3;" : "=l"(d) : "l"(a), "l"(b), "l"(c));
    return d;
}
__device__ __forceinline__ ull addf2(ull a, ull b) {
    ull d;
    asm("add.rn.f32x2 %0, %1, %2;" : "=l"(d) : "l"(a), "l"(b));
    return d;
}
__device__ __forceinline__ ull dup2(float x) {
    ull d;
    asm("mov.b64 %0, {%1, %1};" : "=l"(d) : "r"(__float_as_uint(x)));
    return d;
}
__device__ __forceinline__ float lo_f(ull v) { return __uint_as_float((unsigned)(v & 0xffffffffull)); }
__device__ __forceinline__ float hi_f(ull v) { return __uint_as_float((unsigned)(v >> 32)); }
__device__ __forceinline__ float tanh_fast(float x) {
    float r;
    asm("tanh.approx.f32 %0, %1;" : "=f"(r) : "f"(x));
    return r;
}
__device__ __forceinline__ void cp_async16(uint32_t dst, const void* src) {
    asm volatile("cp.async.cg.shared.global [%0], [%1], 16;" :: "r"(dst), "l"(src));
}
#define CP_COMMIT() asm volatile("cp.async.commit_group;")
#define CP_WAIT(n)  asm volatile("cp.async.wait_group %0;" :: "n"(n))

// ---------------------------------------------------------------------------
// Prep.
// ---------------------------------------------------------------------------
__global__ void prep_kernel(const float* __restrict__ Wih_x,
                            const float* __restrict__ Wih_y,
                            const float* __restrict__ bih_x,
                            const float* __restrict__ bhh_x,
                            const float* __restrict__ bih_y,
                            const float* __restrict__ bhh_y) {
    int t = threadIdx.x;
    for (int e = t; e < 4096; e += 256) {
        int c = e >> 6, j = e & 63;
        g_WTx[c * 64 + j] = Wih_x[j * 64 + c];
        g_WTy[c * 64 + j] = Wih_y[j * 64 + c];
    }
    if (t < 64) {
        g_bsdx[t] = dup2(bih_x[t] + bhh_x[t]);
        g_bsdy[t] = dup2(bih_y[t] + bhh_y[t]);
    }
}

// ---------------------------------------------------------------------------
// Fused proj+scan, one pass. 128 threads, 2 sequences per block, 16 chunks
// of 8 steps. Per chunk: proj (in_sh -> pre_sh, r8-style FFMA2 loop) then
// 8 scan steps (r8-exact). Input chunks staged single-buffered, overlapped
// with the scan phase. pre NEVER touches global memory.
// MODE 0: in = x[b][c][h][w] (cp.async), out = g_mid[(b,h)][w][j]
// MODE 1: in = g_mid[(b,h)][w][j] (4x4 LDG transpose), out = g_buf[(b,w)][h][j2]
// ---------------------------------------------------------------------------
template <int MODE>
__global__ __launch_bounds__(128, 4) void fused_kernel(const float* __restrict__ Whh,
                                                       const float* __restrict__ x) {
    __shared__ float W_sh[64][64];     // Wih^T [c][j]       16 KB
    __shared__ float in_sh[64][16];    // [c][pos]            4 KB (pos = sl*8+tt)
    __shared__ float pre_sh[16][64];   // [pos][j]            4 KB
    __shared__ float hbuf[2][2][80];   // [buf][sl][j]       1.3 KB

    int tid = threadIdx.x;
    int sl  = tid >> 6;                // scan: sequence lane
    int j   = tid & 63;                // scan: hidden unit
    int s0  = blockIdx.x * 2;
    int b   = s0 >> 7;
    int p0  = s0 & 127;                // h0 (MODE0) / w0 (MODE1)

    uint32_t shW = (uint32_t)__cvta_generic_to_shared(&W_sh[0][0]);
    uint32_t shI = (uint32_t)__cvta_generic_to_shared(&in_sh[0][0]);

    // Stage Wih^T (1024 granules, 8/thread)
    {
        const float* WT = (MODE == 0) ? g_WTx : g_WTy;
        #pragma unroll
        for (int i = 0; i < 8; i++) {
            int e = tid + i * 128;
            cp_async16(shW + e * 16, WT + e * 4);
        }
    }

    // Whh row j as 32 k-pair ulls (r8-exact)
    ull w2[32];
    {
        const ull* wr = (const ull*)(Whh + j * 64);
        #pragma unroll
        for (int i = 0; i < 32; i++) w2[i] = wr[i];
    }

    hbuf[0][sl][j] = 0.f;

    // MODE0 source base (x is only used when MODE==0)
    const float* xbase = (MODE == 0) ? (x + (size_t)b * 1048576 + (size_t)p0 * 128)
                                     : nullptr;

    // ---- stage chunk 0 ----
    if (MODE == 0) {
        #pragma unroll
        for (int i = 0; i < 2; i++) {
            int g = tid + i * 128;             // 0..255 granules
            int c = g >> 2, s2 = (g >> 1) & 1, q = g & 1;
            cp_async16(shI + (c * 16 + s2 * 8 + q * 4) * 4,
                       xbase + (size_t)c * 16384 + s2 * 128 + q * 4);
        }
        CP_COMMIT();
        CP_WAIT(0);
    } else {
        if (tid < 64) {
            int j4 = tid & 15, s2 = (tid >> 4) & 1, t4 = tid >> 5;
            const float* p = g_mid + (size_t)(b * 128 + t4 * 4) * 8192
                           + (size_t)(p0 + s2) * 64 + j4 * 4;
            float4 r0 = *(const float4*)(p + 0 * 8192);
            float4 r1 = *(const float4*)(p + 1 * 8192);
            float4 r2 = *(const float4*)(p + 2 * 8192);
            float4 r3 = *(const float4*)(p + 3 * 8192);
            int pc = s2 * 8 + t4 * 4;
            *(float4*)&in_sh[j4 * 4 + 0][pc] = make_float4(r0.x, r1.x, r2.x, r3.x);
            *(float4*)&in_sh[j4 * 4 + 1][pc] = make_float4(r0.y, r1.y, r2.y, r3.y);
            *(float4*)&in_sh[j4 * 4 + 2][pc] = make_float4(r0.z, r1.z, r2.z, r3.z);
            *(float4*)&in_sh[j4 * 4 + 3][pc] = make_float4(r0.w, r1.w, r2.w, r3.w);
        }
        CP_WAIT(0);                            // W_sh staging
    }
    __syncthreads();

    // proj thread mapping
    int pt = tid >> 4;                         // 8 groups, 2 positions each
    int jt = tid & 15;                         // 4 outputs each
    const ull* bd = ((MODE == 0) ? g_bsdx : g_bsdy) + jt * 4;

    // output pointer (scan phase)
    float* outp = ((MODE == 0) ? g_mid : g_buf) + (size_t)(s0 + sl) * 8192 + j;

    int cur = 0;
    for (int k = 0; k < 16; k++) {
        // ---- proj: in_sh -> accumulators ----
        ull a0 = bd[0], a1 = bd[1], a2 = bd[2], a3 = bd[3];
        #pragma unroll 16
        for (int c = 0; c < 64; c++) {
            ull X = *(const ull*)&in_sh[c][pt * 2];     // positions 2pt, 2pt+1
            float4 wv = *(const float4*)&W_sh[c][jt * 4];
            a0 = ffma2(X, dup2(wv.x), a0);
            a1 = ffma2(X, dup2(wv.y), a1);
            a2 = ffma2(X, dup2(wv.z), a2);
            a3 = ffma2(X, dup2(wv.w), a3);
        }
        __syncthreads();                        // everyone done reading in_sh

        // ---- stage chunk k+1 into in_sh (now free) ----
        if (k < 15) {
            if (MODE == 0) {
                #pragma unroll
                for (int i = 0; i < 2; i++) {
                    int g = tid + i * 128;
                    int c = g >> 2, s2 = (g >> 1) & 1, q = g & 1;
                    cp_async16(shI + (c * 16 + s2 * 8 + q * 4) * 4,
                               xbase + (size_t)c * 16384 + s2 * 128 + (k + 1) * 8 + q * 4);
                }
                CP_COMMIT();
            } else {
                if (tid < 64) {
                    int j4 = tid & 15, s2 = (tid >> 4) & 1, t4 = tid >> 5;
                    const float* p = g_mid + (size_t)(b * 128 + (k + 1) * 8 + t4 * 4) * 8192
                                   + (size_t)(p0 + s2) * 64 + j4 * 4;
                    float4 r0 = *(const float4*)(p + 0 * 8192);
                    float4 r1 = *(const float4*)(p + 1 * 8192);
                    float4 r2 = *(const float4*)(p + 2 * 8192);
                    float4 r3 = *(const float4*)(p + 3 * 8192);
                    int pc = s2 * 8 + t4 * 4;
                    *(float4*)&in_sh[j4 * 4 + 0][pc] = make_float4(r0.x, r1.x, r2.x, r3.x);
                    *(float4*)&in_sh[j4 * 4 + 1][pc] = make_float4(r0.y, r1.y, r2.y, r3.y);
                    *(float4*)&in_sh[j4 * 4 + 2][pc] = make_float4(r0.z, r1.z, r2.z, r3.z);
                    *(float4*)&in_sh[j4 * 4 + 3][pc] = make_float4(r0.w, r1.w, r2.w, r3.w);
                }
            }
        }

        // ---- write proj results to pre_sh ----
        {
            float* d0 = &pre_sh[pt * 2 + 0][jt * 4];
            float* d1 = &pre_sh[pt * 2 + 1][jt * 4];
            *(float4*)d0 = make_float4(lo_f(a0), lo_f(a1), lo_f(a2), lo_f(a3));
            *(float4*)d1 = make_float4(hi_f(a0), hi_f(a1), hi_f(a2), hi_f(a3));
        }
        __syncthreads();                        // pre_sh visible (+ MODE1 staging STS done)

        // ---- scan 8 steps (r8-exact inner loop) ----
        const float* pvp = &pre_sh[sl * 8][j];
        #pragma unroll 2
        for (int tt = 0; tt < 8; tt++) {
            float pv = pvp[tt * 64];

            const ulonglong2* h2 = (const ulonglong2*)hbuf[cur][sl];
            ull b0 = 0, b1 = 0, b2 = 0, b3 = 0;
            #pragma unroll
            for (int i = 0; i < 16; i += 2) {
                ulonglong2 ha = h2[i];
                b0 = ffma2(w2[2 * i],     ha.x, b0);
                b1 = ffma2(w2[2 * i + 1], ha.y, b1);
                ulonglong2 hb = h2[i + 1];
                b2 = ffma2(w2[2 * i + 2], hb.x, b2);
                b3 = ffma2(w2[2 * i + 3], hb.y, b3);
            }
            b0 = addf2(b0, b1);
            b2 = addf2(b2, b3);
            b0 = addf2(b0, b2);
            float s_ = pv + lo_f(b0) + hi_f(b0);
            float hn = tanh_fast(s_);

            int nxt = cur ^ 1;
            hbuf[nxt][sl][j] = hn;
            __syncthreads();

            int t = k * 8 + tt;
            outp[(size_t)t * 64] = hn;          // coalesced natural store
            cur = nxt;
        }

        if (MODE == 0 && k < 15) CP_WAIT(0);    // chunk k+1 landed
        __syncthreads();                        // pre_sh reads done; in_sh chunk visible
    }
}

// ---------------------------------------------------------------------------
// Transpose epilogue (r14-proven): g_buf[(b,w)][h][j] -> out[b][j][h][w].
// ---------------------------------------------------------------------------
__global__ __launch_bounds__(256) void transpose_kernel(float* __restrict__ out) {
    __shared__ float tile[8][8][68];   // [ti(h)][wi][j], pad 68

    int tid = threadIdx.x;
    int blk = blockIdx.x;              // b*256 + tt*16 + wt
    int b  = blk >> 8;
    int tt = (blk >> 4) & 15;
    int wt = blk & 15;

    const float* src = g_buf + (size_t)(b * 128 + wt * 8) * 8192 + (size_t)(tt * 8) * 64;

    #pragma unroll
    for (int i = 0; i < 4; i++) {
        int e = tid + i * 256;                 // 0..1023 granules
        int row = e >> 4;
        int ti = row >> 3, wi = row & 7;
        int j4 = e & 15;
        float4 v = *(const float4*)(src + (size_t)wi * 8192 + ti * 64 + j4 * 4);
        *(float4*)&tile[ti][wi][j4 * 4] = v;
    }
    __syncthreads();

    #pragma unroll
    for (int i = 0; i < 2; i++) {
        int task = tid + i * 256;              // 0..511
        int ti = task >> 6;
        int j  = task & 63;
        float4 v0, v1;
        v0.x = tile[ti][0][j]; v0.y = tile[ti][1][j];
        v0.z = tile[ti][2][j]; v0.w = tile[ti][3][j];
        v1.x = tile[ti][4][j]; v1.y = tile[ti][5][j];
        v1.z = tile[ti][6][j]; v1.w = tile[ti][7][j];
        float* d = out + (size_t)b * 1048576 + (size_t)j * 16384
                 + (size_t)(tt * 8 + ti) * 128 + wt * 8;
        *(float4*)(d)     = v0;
        *(float4*)(d + 4) = v1;
    }
}

// ---------------------------------------------------------------------------
extern "C" void kernel_launch(void* const* d_in, const int* in_sizes, int n_in,
                              void* d_out, int out_size) {
    const float* x     = (const float*)d_in[0];
    const float* Wih_x = (const float*)d_in[1];
    const float* Whh_x = (const float*)d_in[2];
    const float* bih_x = (const float*)d_in[3];
    const float* bhh_x = (const float*)d_in[4];
    const float* Wih_y = (const float*)d_in[5];
    const float* Whh_y = (const float*)d_in[6];
    const float* bih_y = (const float*)d_in[7];
    const float* bhh_y = (const float*)d_in[8];
    float* out = (float*)d_out;

    prep_kernel<<<1, 256>>>(Wih_x, Wih_y, bih_x, bhh_x, bih_y, bhh_y);
    fused_kernel<0><<<1024, 128>>>(Whh_x, x);      // x -> g_mid [(b,h)][w][j]
    fused_kernel<1><<<1024, 128>>>(Whh_y, nullptr);// g_mid -> g_buf [(b,w)][h][j2]
    transpose_kernel<<<4096, 256>>>(out);          // g_buf -> out [b][j][h][w]
}

// round 16
// speedup vs baseline: 1.2851x; 1.2851x over previous
#include <cuda_runtime.h>
#include <cstdint>

// x: [16, 64, 128, 128] (B, C, H, W), HX = HY = 64.
// Pass 1: 2048 sequences (b,h), T=128 along w.
// Pass 2: 2048 sequences (b,w), T=128 along h.

using ull = unsigned long long;

__device__ float g_pre[2048 * 128 * 64];   // [seq][t][j]
__device__ float g_mid[2048 * 128 * 64];   // [(b,h)][w][j]  natural scan_x output
__device__ float g_WTx[64 * 64];           // Wih_x^T: [c][j]
__device__ float g_WTy[64 * 64];           // Wih_y^T: [j][j2]
__device__ ull   g_bsdx[64];               // dup'd bias sums
__device__ ull   g_bsdy[64];

__device__ __forceinline__ ull ffma2(ull a, ull b, ull c) {
    ull d;
    asm("fma.rn.f32x2 %0, %1, %2, %3;" : "=l"(d) : "l"(a), "l"(b), "l"(c));
    return d;
}
__device__ __forceinline__ ull addf2(ull a, ull b) {
    ull d;
    asm("add.rn.f32x2 %0, %1, %2;" : "=l"(d) : "l"(a), "l"(b));
    return d;
}
__device__ __forceinline__ ull dup2(float x) {
    ull d;
    asm("mov.b64 %0, {%1, %1};" : "=l"(d) : "r"(__float_as_uint(x)));
    return d;
}
__device__ __forceinline__ float lo_f(ull v) { return __uint_as_float((unsigned)(v & 0xffffffffull)); }
__device__ __forceinline__ float hi_f(ull v) { return __uint_as_float((unsigned)(v >> 32)); }
__device__ __forceinline__ float tanh_fast(float x) {
    float r;
    asm("tanh.approx.f32 %0, %1;" : "=f"(r) : "f"(x));
    return r;
}
__device__ __forceinline__ void cp_async16(uint32_t dst, const void* src) {
    asm volatile("cp.async.cg.shared.global [%0], [%1], 16;" :: "r"(dst), "l"(src));
}
#define CP_COMMIT() asm volatile("cp.async.commit_group;")
#define CP_WAIT(n)  asm volatile("cp.async.wait_group %0;" :: "n"(n))

// ---------------------------------------------------------------------------
// Prep.
// ---------------------------------------------------------------------------
__global__ void prep_kernel(const float* __restrict__ Wih_x,
                            const float* __restrict__ Wih_y,
                            const float* __restrict__ bih_x,
                            const float* __restrict__ bhh_x,
                            const float* __restrict__ bih_y,
                            const float* __restrict__ bhh_y) {
    int t = threadIdx.x;
    for (int e = t; e < 4096; e += 256) {
        int c = e >> 6, j = e & 63;
        g_WTx[c * 64 + j] = Wih_x[j * 64 + c];
        g_WTy[c * 64 + j] = Wih_y[j * 64 + c];
    }
    if (t < 64) {
        g_bsdx[t] = dup2(bih_x[t] + bhh_x[t]);
        g_bsdy[t] = dup2(bih_y[t] + bhh_y[t]);
    }
}

// ---------------------------------------------------------------------------
// Shared proj compute (r8-proven).
// ---------------------------------------------------------------------------
template <int PAD>
__device__ __forceinline__ void proj_compute(const float in_sh[64][PAD],
                                             const float W_sh[64][64],
                                             const ull* bsd, int tid, int row) {
    int pt = tid >> 4;    // position group of 8 (broadcast X)
    int jt = tid & 15;    // output group of 4 (conflict-free W)

    const ull* bd = bsd + jt * 4;
    ull a[4][4];
    #pragma unroll
    for (int o = 0; o < 4; o++) {
        ull bv = bd[o];
        a[0][o] = bv; a[1][o] = bv; a[2][o] = bv; a[3][o] = bv;
    }

    #pragma unroll 8
    for (int c = 0; c < 64; c++) {
        ulonglong2 X0 = *(const ulonglong2*)&in_sh[c][pt * 8];
        ulonglong2 X1 = *(const ulonglong2*)&in_sh[c][pt * 8 + 4];
        float4 wv = *(const float4*)&W_sh[c][jt * 4];
        ull w0 = dup2(wv.x), w1 = dup2(wv.y), w2 = dup2(wv.z), w3 = dup2(wv.w);
        a[0][0] = ffma2(X0.x, w0, a[0][0]);  a[1][0] = ffma2(X0.y, w0, a[1][0]);
        a[2][0] = ffma2(X1.x, w0, a[2][0]);  a[3][0] = ffma2(X1.y, w0, a[3][0]);
        a[0][1] = ffma2(X0.x, w1, a[0][1]);  a[1][1] = ffma2(X0.y, w1, a[1][1]);
        a[2][1] = ffma2(X1.x, w1, a[2][1]);  a[3][1] = ffma2(X1.y, w1, a[3][1]);
        a[0][2] = ffma2(X0.x, w2, a[0][2]);  a[1][2] = ffma2(X0.y, w2, a[1][2]);
        a[2][2] = ffma2(X1.x, w2, a[2][2]);  a[3][2] = ffma2(X1.y, w2, a[3][2]);
        a[0][3] = ffma2(X0.x, w3, a[0][3]);  a[1][3] = ffma2(X0.y, w3, a[1][3]);
        a[2][3] = ffma2(X1.x, w3, a[2][3]);  a[3][3] = ffma2(X1.y, w3, a[3][3]);
    }

    float* dst = g_pre + (size_t)row * 8192 + (pt * 8) * 64 + jt * 4;
    #pragma unroll
    for (int pp = 0; pp < 4; pp++) {
        float4 o;
        o = make_float4(lo_f(a[pp][0]), lo_f(a[pp][1]), lo_f(a[pp][2]), lo_f(a[pp][3]));
        *(float4*)(dst + (pp * 2 + 0) * 64) = o;
        o = make_float4(hi_f(a[pp][0]), hi_f(a[pp][1]), hi_f(a[pp][2]), hi_f(a[pp][3]));
        *(float4*)(dst + (pp * 2 + 1) * 64) = o;
    }
}

// ---------------------------------------------------------------------------
// proj_x (r12-exact).
// ---------------------------------------------------------------------------
__global__ __launch_bounds__(256) void proj_x_kernel(const float* __restrict__ src) {
    __shared__ float in_sh[64][128];
    __shared__ float W_sh[64][64];

    int tid = threadIdx.x;
    int row = blockIdx.x;
    int b = row >> 7, h = row & 127;
    const float* base = src + (size_t)b * 1048576 + (size_t)h * 128;

    uint32_t shW = (uint32_t)__cvta_generic_to_shared(&W_sh[0][0]);
    uint32_t shI = (uint32_t)__cvta_generic_to_shared(&in_sh[0][0]);
    {
        #pragma unroll
        for (int i = 0; i < 4; i++) {
            int e = tid + i * 256;
            cp_async16(shW + e * 16, g_WTx + e * 4);
        }
        #pragma unroll
        for (int i = 0; i < 8; i++) {
            int e = tid + i * 256;
            int c = e >> 5, g4 = e & 31;
            cp_async16(shI + e * 16, base + (size_t)c * 16384 + g4 * 4);
        }
        CP_COMMIT();
        CP_WAIT(0);
        __syncthreads();
    }
    proj_compute<128>(in_sh, W_sh, g_bsdx, tid, row);
}

// ---------------------------------------------------------------------------
// proj_y (r12-exact): input from g_mid[(b,h)][w][j] via in-register 4x4 transpose.
// ---------------------------------------------------------------------------
__global__ __launch_bounds__(256) void proj_y_kernel() {
    __shared__ float in_sh[64][132];
    __shared__ float W_sh[64][64];

    int tid = threadIdx.x;
    int row = blockIdx.x;              // b*128 + w
    int b = row >> 7, w = row & 127;
    const float* mid_base = g_mid + (size_t)b * 1048576 + (size_t)w * 64;

    uint32_t shW = (uint32_t)__cvta_generic_to_shared(&W_sh[0][0]);
    #pragma unroll
    for (int i = 0; i < 4; i++) {
        int e = tid + i * 256;
        cp_async16(shW + e * 16, g_WTy + e * 4);
    }
    CP_COMMIT();

    #pragma unroll
    for (int i = 0; i < 2; i++) {
        int tl = tid + i * 256;                  // 0..511
        int h4 = tl >> 4, j4 = tl & 15;
        const float* p = mid_base + (size_t)(h4 * 4) * 8192 + j4 * 4;
        float4 r0 = *(const float4*)(p + 0 * 8192);
        float4 r1 = *(const float4*)(p + 1 * 8192);
        float4 r2 = *(const float4*)(p + 2 * 8192);
        float4 r3 = *(const float4*)(p + 3 * 8192);
        *(float4*)&in_sh[j4 * 4 + 0][h4 * 4] = make_float4(r0.x, r1.x, r2.x, r3.x);
        *(float4*)&in_sh[j4 * 4 + 1][h4 * 4] = make_float4(r0.y, r1.y, r2.y, r3.y);
        *(float4*)&in_sh[j4 * 4 + 2][h4 * 4] = make_float4(r0.z, r1.z, r2.z, r3.z);
        *(float4*)&in_sh[j4 * 4 + 3][h4 * 4] = make_float4(r0.w, r1.w, r2.w, r3.w);
    }
    CP_WAIT(0);
    __syncthreads();

    proj_compute<132>(in_sh, W_sh, g_bsdy, tid, row);
}

// ---------------------------------------------------------------------------
// Recurrent scan (r12 structure, DEEPER PIPELINE): 2 seqs per 128-thread
// block; pre staged via 4-buffer cp.async ring with 3 chunks (24KB) in
// flight per block -> 3x the outstanding bytes of r12.
// MODE 0: coalesced natural store g_mid[(b,h)][w][j].
// MODE 1: remap store to out[b][j][h][w] (8B groups).
// ---------------------------------------------------------------------------
template <int MODE>
__global__ __launch_bounds__(128, 4) void scan_kernel(const float* __restrict__ Whh,
                                                      float* __restrict__ out) {
    __shared__ float pre_sh[4][2][16][64];   // [buf][sl][tt][j] 32KB ring
    __shared__ float hbuf[2][2][80];         // pad 80: conflict-free remap

    int tid = threadIdx.x;
    int sl  = tid >> 6;
    int j   = tid & 63;
    int s0  = blockIdx.x * 2;
    int b   = s0 >> 7;
    int p0  = s0 & 127;

    const float* preg = g_pre + (size_t)s0 * 8192;

    ull w2[32];
    {
        const ull* wr = (const ull*)(Whh + j * 64);
        #pragma unroll
        for (int i = 0; i < 32; i++) w2[i] = wr[i];
    }

    hbuf[0][sl][j] = 0.f;

    uint32_t preb = (uint32_t)__cvta_generic_to_shared(&pre_sh[0][0][0][0]);

    // Prologue: stage chunks 0,1,2 (separate commit groups). Chunk = 8KB.
    #pragma unroll
    for (int kc = 0; kc < 3; kc++) {
        #pragma unroll
        for (int i = 0; i < 4; i++) {
            int e = tid * 4 + i * 512;             // 0..2044, 2048 floats
            int seq = e >> 10, off = e & 1023;
            cp_async16(preb + (kc * 8192 + e * 4),
                       preg + (size_t)seq * 8192 + kc * 1024 + off);
        }
        CP_COMMIT();
    }

    float* outp;
    int j2 = 0, s2 = 0;
    if (MODE == 0) {
        outp = g_mid + (size_t)(s0 + sl) * 8192 + j;                       // + t*64
    } else {
        j2 = tid >> 1;  s2 = tid & 1;
        outp = out + (size_t)b * 1048576 + (size_t)j2 * 16384 + p0 + s2;   // + t*128
    }

    int cur = 0;
    for (int k = 0; k < 8; k++) {
        // wait for chunk k: in flight = chunks k..min(k+2,7)
        if (k <= 5)      CP_WAIT(2);
        else if (k == 6) CP_WAIT(1);
        else             CP_WAIT(0);
        __syncthreads();                       // chunk k visible block-wide

        const float* pvp = &pre_sh[k & 3][sl][0][j];

        #pragma unroll 4
        for (int tt = 0; tt < 16; tt++) {
            float pv = pvp[tt * 64];

            const ulonglong2* h2 = (const ulonglong2*)hbuf[cur][sl];
            ull a0 = 0, a1 = 0, a2 = 0, a3 = 0;
            #pragma unroll
            for (int i = 0; i < 16; i += 2) {
                ulonglong2 ha = h2[i];
                a0 = ffma2(w2[2 * i],     ha.x, a0);
                a1 = ffma2(w2[2 * i + 1], ha.y, a1);
                ulonglong2 hb = h2[i + 1];
                a2 = ffma2(w2[2 * i + 2], hb.x, a2);
                a3 = ffma2(w2[2 * i + 3], hb.y, a3);
            }
            a0 = addf2(a0, a1);
            a2 = addf2(a2, a3);
            a0 = addf2(a0, a2);
            float s_ = pv + lo_f(a0) + hi_f(a0);
            float hn = tanh_fast(s_);

            int nxt = cur ^ 1;
            hbuf[nxt][sl][j] = hn;
            __syncthreads();

            int t = k * 16 + tt;
            if (MODE == 0) {
                outp[(size_t)t * 64] = hn;          // coalesced 512B/block
            } else {
                float v = hbuf[nxt][s2][j2];        // conflict-free remap
                outp[(size_t)t * 128] = v;
            }

            cur = nxt;
        }

        // issue chunk k+3 into buf (k+3)&3 (consumed at iteration k-1)
        if (k < 5) {
            int kc = k + 3;
            #pragma unroll
            for (int i = 0; i < 4; i++) {
                int e = tid * 4 + i * 512;
                int seq = e >> 10, off = e & 1023;
                cp_async16(preb + ((kc & 3) * 8192 + e * 4),
                           preg + (size_t)seq * 8192 + kc * 1024 + off);
            }
            CP_COMMIT();
        }
    }
}

// ---------------------------------------------------------------------------
extern "C" void kernel_launch(void* const* d_in, const int* in_sizes, int n_in,
                              void* d_out, int out_size) {
    const float* x     = (const float*)d_in[0];
    const float* Wih_x = (const float*)d_in[1];
    const float* Whh_x = (const float*)d_in[2];
    const float* bih_x = (const float*)d_in[3];
    const float* bhh_x = (const float*)d_in[4];
    const float* Wih_y = (const float*)d_in[5];
    const float* Whh_y = (const float*)d_in[6];
    const float* bih_y = (const float*)d_in[7];
    const float* bhh_y = (const float*)d_in[8];
    float* out = (float*)d_out;

    prep_kernel<<<1, 256>>>(Wih_x, Wih_y, bih_x, bhh_x, bih_y, bhh_y);
    proj_x_kernel<<<2048, 256>>>(x);                   // pre_x [(b,h)][w][j]
    scan_kernel<0><<<1024, 128>>>(Whh_x, nullptr);     // scan w -> g_mid natural
    proj_y_kernel<<<2048, 256>>>();                    // pre_y [(b,w)][h][j2]
    scan_kernel<1><<<1024, 128>>>(Whh_y, out);         // scan h -> out [b][j][h][w]
}

// round 17
// speedup vs baseline: 1.2878x; 1.0021x over previous
#include <cuda_runtime.h>
#include <cstdint>

// x: [16, 64, 128, 128] (B, C, H, W), HX = HY = 64.
// Pass 1: 2048 sequences (b,h), T=128 along w.
// Pass 2: 2048 sequences (b,w), T=128 along h.

using ull = unsigned long long;

__device__ float g_pre[2048 * 128 * 64];   // [seq][t][j]
__device__ float g_mid[2048 * 128 * 64];   // [(b,h)][w][j]  natural scan_x output
__device__ float g_WTx[64 * 64];           // Wih_x^T: [c][j]
__device__ float g_WTy[64 * 64];           // Wih_y^T: [j][j2]
__device__ ull   g_bsdx[64];               // dup'd bias sums
__device__ ull   g_bsdy[64];

__device__ __forceinline__ ull ffma2(ull a, ull b, ull c) {
    ull d;
    asm("fma.rn.f32x2 %0, %1, %2, %3;" : "=l"(d) : "l"(a), "l"(b), "l"(c));
    return d;
}
__device__ __forceinline__ ull addf2(ull a, ull b) {
    ull d;
    asm("add.rn.f32x2 %0, %1, %2;" : "=l"(d) : "l"(a), "l"(b));
    return d;
}
__device__ __forceinline__ ull dup2(float x) {
    ull d;
    asm("mov.b64 %0, {%1, %1};" : "=l"(d) : "r"(__float_as_uint(x)));
    return d;
}
__device__ __forceinline__ float lo_f(ull v) { return __uint_as_float((unsigned)(v & 0xffffffffull)); }
__device__ __forceinline__ float hi_f(ull v) { return __uint_as_float((unsigned)(v >> 32)); }
__device__ __forceinline__ float tanh_fast(float x) {
    float r;
    asm("tanh.approx.f32 %0, %1;" : "=f"(r) : "f"(x));
    return r;
}
__device__ __forceinline__ void cp_async16(uint32_t dst, const void* src) {
    asm volatile("cp.async.cg.shared.global [%0], [%1], 16;" :: "r"(dst), "l"(src));
}
#define CP_COMMIT() asm volatile("cp.async.commit_group;")
#define CP_WAIT(n)  asm volatile("cp.async.wait_group %0;" :: "n"(n))

// ---------------------------------------------------------------------------
// Prep.
// ---------------------------------------------------------------------------
__global__ void prep_kernel(const float* __restrict__ Wih_x,
                            const float* __restrict__ Wih_y,
                            const float* __restrict__ bih_x,
                            const float* __restrict__ bhh_x,
                            const float* __restrict__ bih_y,
                            const float* __restrict__ bhh_y) {
    int t = threadIdx.x;
    for (int e = t; e < 4096; e += 256) {
        int c = e >> 6, j = e & 63;
        g_WTx[c * 64 + j] = Wih_x[j * 64 + c];
        g_WTy[c * 64 + j] = Wih_y[j * 64 + c];
    }
    if (t < 64) {
        g_bsdx[t] = dup2(bih_x[t] + bhh_x[t]);
        g_bsdy[t] = dup2(bih_y[t] + bhh_y[t]);
    }
}

// ---------------------------------------------------------------------------
// Shared proj compute (r8-proven).
// ---------------------------------------------------------------------------
template <int PAD>
__device__ __forceinline__ void proj_compute(const float in_sh[64][PAD],
                                             const float W_sh[64][64],
                                             const ull* bsd, int tid, int row) {
    int pt = tid >> 4;    // position group of 8 (broadcast X)
    int jt = tid & 15;    // output group of 4 (conflict-free W)

    const ull* bd = bsd + jt * 4;
    ull a[4][4];
    #pragma unroll
    for (int o = 0; o < 4; o++) {
        ull bv = bd[o];
        a[0][o] = bv; a[1][o] = bv; a[2][o] = bv; a[3][o] = bv;
    }

    #pragma unroll 8
    for (int c = 0; c < 64; c++) {
        ulonglong2 X0 = *(const ulonglong2*)&in_sh[c][pt * 8];
        ulonglong2 X1 = *(const ulonglong2*)&in_sh[c][pt * 8 + 4];
        float4 wv = *(const float4*)&W_sh[c][jt * 4];
        ull w0 = dup2(wv.x), w1 = dup2(wv.y), w2 = dup2(wv.z), w3 = dup2(wv.w);
        a[0][0] = ffma2(X0.x, w0, a[0][0]);  a[1][0] = ffma2(X0.y, w0, a[1][0]);
        a[2][0] = ffma2(X1.x, w0, a[2][0]);  a[3][0] = ffma2(X1.y, w0, a[3][0]);
        a[0][1] = ffma2(X0.x, w1, a[0][1]);  a[1][1] = ffma2(X0.y, w1, a[1][1]);
        a[2][1] = ffma2(X1.x, w1, a[2][1]);  a[3][1] = ffma2(X1.y, w1, a[3][1]);
        a[0][2] = ffma2(X0.x, w2, a[0][2]);  a[1][2] = ffma2(X0.y, w2, a[1][2]);
        a[2][2] = ffma2(X1.x, w2, a[2][2]);  a[3][2] = ffma2(X1.y, w2, a[3][2]);
        a[0][3] = ffma2(X0.x, w3, a[0][3]);  a[1][3] = ffma2(X0.y, w3, a[1][3]);
        a[2][3] = ffma2(X1.x, w3, a[2][3]);  a[3][3] = ffma2(X1.y, w3, a[3][3]);
    }

    float* dst = g_pre + (size_t)row * 8192 + (pt * 8) * 64 + jt * 4;
    #pragma unroll
    for (int pp = 0; pp < 4; pp++) {
        float4 o;
        o = make_float4(lo_f(a[pp][0]), lo_f(a[pp][1]), lo_f(a[pp][2]), lo_f(a[pp][3]));
        *(float4*)(dst + (pp * 2 + 0) * 64) = o;
        o = make_float4(hi_f(a[pp][0]), hi_f(a[pp][1]), hi_f(a[pp][2]), hi_f(a[pp][3]));
        *(float4*)(dst + (pp * 2 + 1) * 64) = o;
    }
}

// ---------------------------------------------------------------------------
// proj_x (r12-exact).
// ---------------------------------------------------------------------------
__global__ __launch_bounds__(256) void proj_x_kernel(const float* __restrict__ src) {
    __shared__ float in_sh[64][128];
    __shared__ float W_sh[64][64];

    int tid = threadIdx.x;
    int row = blockIdx.x;
    int b = row >> 7, h = row & 127;
    const float* base = src + (size_t)b * 1048576 + (size_t)h * 128;

    uint32_t shW = (uint32_t)__cvta_generic_to_shared(&W_sh[0][0]);
    uint32_t shI = (uint32_t)__cvta_generic_to_shared(&in_sh[0][0]);
    {
        #pragma unroll
        for (int i = 0; i < 4; i++) {
            int e = tid + i * 256;
            cp_async16(shW + e * 16, g_WTx + e * 4);
        }
        #pragma unroll
        for (int i = 0; i < 8; i++) {
            int e = tid + i * 256;
            int c = e >> 5, g4 = e & 31;
            cp_async16(shI + e * 16, base + (size_t)c * 16384 + g4 * 4);
        }
        CP_COMMIT();
        CP_WAIT(0);
        __syncthreads();
    }
    proj_compute<128>(in_sh, W_sh, g_bsdx, tid, row);
}

// ---------------------------------------------------------------------------
// proj_y (r12-exact): input from g_mid[(b,h)][w][j] via in-register 4x4 transpose.
// ---------------------------------------------------------------------------
__global__ __launch_bounds__(256) void proj_y_kernel() {
    __shared__ float in_sh[64][132];
    __shared__ float W_sh[64][64];

    int tid = threadIdx.x;
    int row = blockIdx.x;              // b*128 + w
    int b = row >> 7, w = row & 127;
    const float* mid_base = g_mid + (size_t)b * 1048576 + (size_t)w * 64;

    uint32_t shW = (uint32_t)__cvta_generic_to_shared(&W_sh[0][0]);
    #pragma unroll
    for (int i = 0; i < 4; i++) {
        int e = tid + i * 256;
        cp_async16(shW + e * 16, g_WTy + e * 4);
    }
    CP_COMMIT();

    #pragma unroll
    for (int i = 0; i < 2; i++) {
        int tl = tid + i * 256;                  // 0..511
        int h4 = tl >> 4, j4 = tl & 15;
        const float* p = mid_base + (size_t)(h4 * 4) * 8192 + j4 * 4;
        float4 r0 = *(const float4*)(p + 0 * 8192);
        float4 r1 = *(const float4*)(p + 1 * 8192);
        float4 r2 = *(const float4*)(p + 2 * 8192);
        float4 r3 = *(const float4*)(p + 3 * 8192);
        *(float4*)&in_sh[j4 * 4 + 0][h4 * 4] = make_float4(r0.x, r1.x, r2.x, r3.x);
        *(float4*)&in_sh[j4 * 4 + 1][h4 * 4] = make_float4(r0.y, r1.y, r2.y, r3.y);
        *(float4*)&in_sh[j4 * 4 + 2][h4 * 4] = make_float4(r0.z, r1.z, r2.z, r3.z);
        *(float4*)&in_sh[j4 * 4 + 3][h4 * 4] = make_float4(r0.w, r1.w, r2.w, r3.w);
    }
    CP_WAIT(0);
    __syncthreads();

    proj_compute<132>(in_sh, W_sh, g_bsdy, tid, row);
}

// ---------------------------------------------------------------------------
// Recurrent scan (r12 structure, DEEPER PIPELINE): 2 seqs per 128-thread
// block; pre staged via 4-buffer cp.async ring with 3 chunks (24KB) in
// flight per block -> 3x the outstanding bytes of r12.
// MODE 0: coalesced natural store g_mid[(b,h)][w][j].
// MODE 1: remap store to out[b][j][h][w] (8B groups).
// ---------------------------------------------------------------------------
template <int MODE>
__global__ __launch_bounds__(128, 4) void scan_kernel(const float* __restrict__ Whh,
                                                      float* __restrict__ out) {
    __shared__ float pre_sh[4][2][16][64];   // [buf][sl][tt][j] 32KB ring
    __shared__ float hbuf[2][2][80];         // pad 80: conflict-free remap

    int tid = threadIdx.x;
    int sl  = tid >> 6;
    int j   = tid & 63;
    int s0  = blockIdx.x * 2;
    int b   = s0 >> 7;
    int p0  = s0 & 127;

    const float* preg = g_pre + (size_t)s0 * 8192;

    ull w2[32];
    {
        const ull* wr = (const ull*)(Whh + j * 64);
        #pragma unroll
        for (int i = 0; i < 32; i++) w2[i] = wr[i];
    }

    hbuf[0][sl][j] = 0.f;

    uint32_t preb = (uint32_t)__cvta_generic_to_shared(&pre_sh[0][0][0][0]);

    // Prologue: stage chunks 0,1,2 (separate commit groups). Chunk = 8KB.
    #pragma unroll
    for (int kc = 0; kc < 3; kc++) {
        #pragma unroll
        for (int i = 0; i < 4; i++) {
            int e = tid * 4 + i * 512;             // 0..2044, 2048 floats
            int seq = e >> 10, off = e & 1023;
            cp_async16(preb + (kc * 8192 + e * 4),
                       preg + (size_t)seq * 8192 + kc * 1024 + off);
        }
        CP_COMMIT();
    }

    float* outp;
    int j2 = 0, s2 = 0;
    if (MODE == 0) {
        outp = g_mid + (size_t)(s0 + sl) * 8192 + j;                       // + t*64
    } else {
        j2 = tid >> 1;  s2 = tid & 1;
        outp = out + (size_t)b * 1048576 + (size_t)j2 * 16384 + p0 + s2;   // + t*128
    }

    int cur = 0;
    for (int k = 0; k < 8; k++) {
        // wait for chunk k: in flight = chunks k..min(k+2,7)
        if (k <= 5)      CP_WAIT(2);
        else if (k == 6) CP_WAIT(1);
        else             CP_WAIT(0);
        __syncthreads();                       // chunk k visible block-wide

        const float* pvp = &pre_sh[k & 3][sl][0][j];

        #pragma unroll 4
        for (int tt = 0; tt < 16; tt++) {
            float pv = pvp[tt * 64];

            const ulonglong2* h2 = (const ulonglong2*)hbuf[cur][sl];
            ull a0 = 0, a1 = 0, a2 = 0, a3 = 0;
            #pragma unroll
            for (int i = 0; i < 16; i += 2) {
                ulonglong2 ha = h2[i];
                a0 = ffma2(w2[2 * i],     ha.x, a0);
                a1 = ffma2(w2[2 * i + 1], ha.y, a1);
                ulonglong2 hb = h2[i + 1];
                a2 = ffma2(w2[2 * i + 2], hb.x, a2);
                a3 = ffma2(w2[2 * i + 3], hb.y, a3);
            }
            a0 = addf2(a0, a1);
            a2 = addf2(a2, a3);
            a0 = addf2(a0, a2);
            float s_ = pv + lo_f(a0) + hi_f(a0);
            float hn = tanh_fast(s_);

            int nxt = cur ^ 1;
            hbuf[nxt][sl][j] = hn;
            __syncthreads();

            int t = k * 16 + tt;
            if (MODE == 0) {
                outp[(size_t)t * 64] = hn;          // coalesced 512B/block
            } else {
                float v = hbuf[nxt][s2][j2];        // conflict-free remap
                outp[(size_t)t * 128] = v;
            }

            cur = nxt;
        }

        // issue chunk k+3 into buf (k+3)&3 (consumed at iteration k-1)
        if (k < 5) {
            int kc = k + 3;
            #pragma unroll
            for (int i = 0; i < 4; i++) {
                int e = tid * 4 + i * 512;
                int seq = e >> 10, off = e & 1023;
                cp_async16(preb + ((kc & 3) * 8192 + e * 4),
                           preg + (size_t)seq * 8192 + kc * 1024 + off);
            }
            CP_COMMIT();
        }
    }
}

// ---------------------------------------------------------------------------
extern "C" void kernel_launch(void* const* d_in, const int* in_sizes, int n_in,
                              void* d_out, int out_size) {
    const float* x     = (const float*)d_in[0];
    const float* Wih_x = (const float*)d_in[1];
    const float* Whh_x = (const float*)d_in[2];
    const float* bih_x = (const float*)d_in[3];
    const float* bhh_x = (const float*)d_in[4];
    const float* Wih_y = (const float*)d_in[5];
    const float* Whh_y = (const float*)d_in[6];
    const float* bih_y = (const float*)d_in[7];
    const float* bhh_y = (const float*)d_in[8];
    float* out = (float*)d_out;

    prep_kernel<<<1, 256>>>(Wih_x, Wih_y, bih_x, bhh_x, bih_y, bhh_y);
    proj_x_kernel<<<2048, 256>>>(x);                   // pre_x [(b,h)][w][j]
    scan_kernel<0><<<1024, 128>>>(Whh_x, nullptr);     // scan w -> g_mid natural
    proj_y_kernel<<<2048, 256>>>();                    // pre_y [(b,w)][h][j2]
    scan_kernel<1><<<1024, 128>>>(Whh_y, out);         // scan h -> out [b][j][h][w]
}